// round 10
// baseline (speedup 1.0000x reference)
#include <cuda_runtime.h>
#include <math.h>
#include <stdint.h>

#define B_ 64
#define T_ 1024
#define H_ 256
#define M_ (B_*T_)   /* 65536 rows for the projection GEMMs */

// Scratch (device globals — no runtime allocation allowed)
__device__ float g_xp[B_*T_*H_];   // input-projection result for current layer
__device__ float g_h [B_*T_*H_];   // layer-0 hidden sequence

// ---------------------------------------------------------------------------
// packed f32x2 helpers (sm_100+): one instr = 2 fp32 FMAs
// ---------------------------------------------------------------------------
__device__ __forceinline__ unsigned long long ffma2(unsigned long long a,
                                                    unsigned long long b,
                                                    unsigned long long c) {
    unsigned long long d;
    asm("fma.rn.f32x2 %0, %1, %2, %3;" : "=l"(d) : "l"(a), "l"(b), "l"(c));
    return d;
}
__device__ __forceinline__ unsigned long long pack2(float lo, float hi) {
    unsigned long long r;
    asm("mov.b64 %0, {%1, %2};"
        : "=l"(r) : "r"(__float_as_uint(lo)), "r"(__float_as_uint(hi)));
    return r;
}
__device__ __forceinline__ float2 unpack2(unsigned long long v) {
    uint32_t lo, hi;
    asm("mov.b64 {%0, %1}, %2;" : "=r"(lo), "=r"(hi) : "l"(v));
    return make_float2(__uint_as_float(lo), __uint_as_float(hi));
}
// Fast accurate-enough tanh: ~1e-7 rel err, MUFU-based (no branches).
__device__ __forceinline__ float tanh_fast(float x) {
    float xc = fminf(fmaxf(x, -9.0f), 9.0f);     // tanh(9)=1-3e-8
    float e  = __expf(2.0f * xc);
    return __fdividef(e - 1.0f, e + 1.0f);
}

// ---------------------------------------------------------------------------
// Projection GEMM: out[M,256] = A[M,256] @ W[256,256]^T + bias
// (unchanged: ~214us each)
// ---------------------------------------------------------------------------
__global__ void __launch_bounds__(256, 2)
gemm_bias(const float* __restrict__ A, const float* __restrict__ W,
          const float* __restrict__ bias, float* __restrict__ out)
{
    __shared__ __align__(16) float As[16][128];
    __shared__ __align__(16) float Bs[16][64];

    const int tid = threadIdx.x;
    const int m0  = blockIdx.x * 128;
    const int n0  = blockIdx.y * 64;
    const int tx  = tid & 15;
    const int ty  = tid >> 4;
    const int lm  = tid >> 1;
    const int ak  = (tid & 1) * 8;
    const int ln  = tid & 63;
    const int bk  = (tid >> 6) * 4;

    unsigned long long acc[4][4];
#pragma unroll
    for (int p = 0; p < 4; p++)
#pragma unroll
        for (int n = 0; n < 4; n++) acc[p][n] = 0ull;

    const float* Arow = A + (size_t)(m0 + lm) * H_;
    const float* Wrow = W + (size_t)(n0 + ln) * H_;

    for (int k0 = 0; k0 < H_; k0 += 16) {
        float4 av0 = *(const float4*)(Arow + k0 + ak);
        float4 av1 = *(const float4*)(Arow + k0 + ak + 4);
        float4 bv0 = *(const float4*)(Wrow + k0 + bk);
        As[ak+0][lm] = av0.x; As[ak+1][lm] = av0.y;
        As[ak+2][lm] = av0.z; As[ak+3][lm] = av0.w;
        As[ak+4][lm] = av1.x; As[ak+5][lm] = av1.y;
        As[ak+6][lm] = av1.z; As[ak+7][lm] = av1.w;
        Bs[bk+0][ln] = bv0.x; Bs[bk+1][ln] = bv0.y;
        Bs[bk+2][ln] = bv0.z; Bs[bk+3][ln] = bv0.w;
        __syncthreads();
#pragma unroll
        for (int k = 0; k < 16; k++) {
            const ulonglong2* ap = (const ulonglong2*)&As[k][ty * 8];
            ulonglong2 q0 = ap[0];
            ulonglong2 q1 = ap[1];
            float4 bv = *(const float4*)&Bs[k][tx * 4];
            unsigned long long b0 = pack2(bv.x, bv.x);
            unsigned long long b1 = pack2(bv.y, bv.y);
            unsigned long long b2 = pack2(bv.z, bv.z);
            unsigned long long b3 = pack2(bv.w, bv.w);
            acc[0][0]=ffma2(q0.x,b0,acc[0][0]); acc[0][1]=ffma2(q0.x,b1,acc[0][1]);
            acc[0][2]=ffma2(q0.x,b2,acc[0][2]); acc[0][3]=ffma2(q0.x,b3,acc[0][3]);
            acc[1][0]=ffma2(q0.y,b0,acc[1][0]); acc[1][1]=ffma2(q0.y,b1,acc[1][1]);
            acc[1][2]=ffma2(q0.y,b2,acc[1][2]); acc[1][3]=ffma2(q0.y,b3,acc[1][3]);
            acc[2][0]=ffma2(q1.x,b0,acc[2][0]); acc[2][1]=ffma2(q1.x,b1,acc[2][1]);
            acc[2][2]=ffma2(q1.x,b2,acc[2][2]); acc[2][3]=ffma2(q1.x,b3,acc[2][3]);
            acc[3][0]=ffma2(q1.y,b0,acc[3][0]); acc[3][1]=ffma2(q1.y,b1,acc[3][1]);
            acc[3][2]=ffma2(q1.y,b2,acc[3][2]); acc[3][3]=ffma2(q1.y,b3,acc[3][3]);
        }
        __syncthreads();
    }

    float4 bb = *(const float4*)(bias + n0 + tx * 4);
#pragma unroll
    for (int p = 0; p < 4; p++) {
        float2 c0 = unpack2(acc[p][0]);
        float2 c1 = unpack2(acc[p][1]);
        float2 c2 = unpack2(acc[p][2]);
        float2 c3 = unpack2(acc[p][3]);
        float4 lo = make_float4(c0.x + bb.x, c1.x + bb.y, c2.x + bb.z, c3.x + bb.w);
        float4 hi = make_float4(c0.y + bb.x, c1.y + bb.y, c2.y + bb.z, c3.y + bb.w);
        size_t r = (size_t)(m0 + ty * 8 + 2 * p) * H_ + n0 + tx * 4;
        *(float4*)(out + r)      = lo;
        *(float4*)(out + r + H_) = hi;
    }
}

// ---------------------------------------------------------------------------
// Recurrent scan, round 10: SINGLE-CTA, 512 threads, whole W_hh in one RF.
//  Insight from rounds 8+9 decomposition: step = compute(~880) + DSMEM
//  handshake(~600). At 512 threads, W_hh (64K fp32) fits exactly in one
//  CTA's register file (512 x 64 regs), so the cluster — and its 600-cyc
//  handshake — is deleted entirely. Per-step sync is ONE 512-thread
//  bar.sync. 4 warps/SMSP (vs 2) also doubles latency hiding on the
//  LDS/FFMA chains.
//  Thread t: output j=t>>1, k-half kpar=t&1 (64 packed f32x2 weights).
//  2-way combine = shfl.xor(1); even thread does tanh + STS + STG.
//  hs halves padded 136 floats apart -> even/odd lanes hit disjoint banks.
//  One CTA per batch: grid=64.
// ---------------------------------------------------------------------------
__global__ void __launch_bounds__(512, 1)
elman_scan(const float* __restrict__ xp, const float* __restrict__ Whh,
           float* __restrict__ ys)
{
    __shared__ __align__(16) float hs[2][2][136];   // [buf][khalf][128+8 pad]

    const int tid  = threadIdx.x;
    const int kpar = tid & 1;          // k-half this thread reduces
    const int j    = tid >> 1;         // output index [0,256)
    const int jhi  = j >> 7;           // which h-half j belongs to
    const int jlo  = j & 127;
    const int batch = (int)blockIdx.x;

    // Weights: W_hh[j][kpar*128 .. +127] as 64 packed f32x2
    unsigned long long w[64];
    {
        const ulonglong2* wv =
            (const ulonglong2*)(Whh + (size_t)j * H_ + kpar * 128);
#pragma unroll
        for (int i = 0; i < 32; i++) {
            ulonglong2 v = wv[i];
            w[2*i] = v.x; w[2*i+1] = v.y;
        }
    }

    for (int i = tid; i < 2 * 2 * 136; i += 512) (&hs[0][0][0])[i] = 0.0f;
    __syncthreads();

    const float* xpb = xp + (size_t)batch * T_ * H_;
    float*       ysb = ys + (size_t)batch * T_ * H_;

    float x_cur = 0.0f, x_next = 0.0f;
    if (kpar == 0) x_cur = __ldg(xpb + j);   // xp[t=0][j]

    for (int t = 0; t < T_; t++) {
        // Prefetch next xp early (hides L2 latency under the FFMA chain)
        if (kpar == 0 && t + 1 < T_)
            x_next = __ldg(xpb + (size_t)(t + 1) * H_ + j);

        // Dot over this thread's k-half: LDS broadcast (2 groups, no bank
        // conflicts thanks to the 136-float half stride)
        const ulonglong2* hv = (const ulonglong2*)&hs[t & 1][kpar][0];
        unsigned long long a0 = 0ull, a1 = 0ull, a2 = 0ull, a3 = 0ull;
#pragma unroll
        for (int i = 0; i < 16; i++) {
            ulonglong2 p = hv[2*i];
            ulonglong2 q = hv[2*i + 1];
            a0 = ffma2(w[4*i+0], p.x, a0);
            a1 = ffma2(w[4*i+1], p.y, a1);
            a2 = ffma2(w[4*i+2], q.x, a2);
            a3 = ffma2(w[4*i+3], q.y, a3);
        }
        float2 f0 = unpack2(a0), f1 = unpack2(a1);
        float2 f2 = unpack2(a2), f3 = unpack2(a3);
        float s = ((f0.x + f0.y) + (f1.x + f1.y)) +
                  ((f2.x + f2.y) + (f3.x + f3.y));
        float tot = s + __shfl_xor_sync(0xFFFFFFFFu, s, 1);

        if (kpar == 0) {
            float v = tanh_fast(tot + x_cur);
            hs[(t + 1) & 1][jhi][jlo] = v;
            ysb[(size_t)t * H_ + j] = v;
            x_cur = x_next;
        }
        __syncthreads();   // h[t+1] visible; also orders buf reuse (WAR)
    }
}

// ---------------------------------------------------------------------------
// Launch: gemm0 -> scan0 -> gemm1 -> scan1 (all on the capture stream)
// ---------------------------------------------------------------------------
extern "C" void kernel_launch(void* const* d_in, const int* in_sizes, int n_in,
                              void* d_out, int out_size)
{
    const float* x     = (const float*)d_in[0];
    const float* W_ih0 = (const float*)d_in[1];
    const float* b_ih0 = (const float*)d_in[2];
    const float* W_hh0 = (const float*)d_in[3];
    const float* W_ih1 = (const float*)d_in[4];
    const float* b_ih1 = (const float*)d_in[5];
    const float* W_hh1 = (const float*)d_in[6];
    float* out = (float*)d_out;

    float *xp, *h;
    cudaGetSymbolAddress((void**)&xp, g_xp);
    cudaGetSymbolAddress((void**)&h,  g_h);

    dim3 ggrid(M_ / 128, H_ / 64);   // (512, 4)

    gemm_bias<<<ggrid, 256>>>(x, W_ih0, b_ih0, xp);
    elman_scan<<<B_, 512>>>(xp, W_hh0, h);
    gemm_bias<<<ggrid, 256>>>(h, W_ih1, b_ih1, xp);
    elman_scan<<<B_, 512>>>(xp, W_hh1, out);
}

// round 11
// speedup vs baseline: 1.2896x; 1.2896x over previous
#include <cuda_runtime.h>
#include <math.h>
#include <stdint.h>

#define B_ 64
#define T_ 1024
#define H_ 256
#define M_ (B_*T_)   /* 65536 rows for the projection GEMMs */
#define NB 2         /* batches interleaved per cluster */

// Scratch (device globals — no runtime allocation allowed)
__device__ float g_xp[B_*T_*H_];   // input-projection result for current layer
__device__ float g_h [B_*T_*H_];   // layer-0 hidden sequence

// ---------------------------------------------------------------------------
// packed f32x2 helpers (sm_100+): one instr = 2 fp32 FMAs
// ---------------------------------------------------------------------------
__device__ __forceinline__ unsigned long long ffma2(unsigned long long a,
                                                    unsigned long long b,
                                                    unsigned long long c) {
    unsigned long long d;
    asm("fma.rn.f32x2 %0, %1, %2, %3;" : "=l"(d) : "l"(a), "l"(b), "l"(c));
    return d;
}
__device__ __forceinline__ unsigned long long pack2(float lo, float hi) {
    unsigned long long r;
    asm("mov.b64 %0, {%1, %2};"
        : "=l"(r) : "r"(__float_as_uint(lo)), "r"(__float_as_uint(hi)));
    return r;
}
__device__ __forceinline__ float2 unpack2(unsigned long long v) {
    uint32_t lo, hi;
    asm("mov.b64 {%0, %1}, %2;" : "=r"(lo), "=r"(hi) : "l"(v));
    return make_float2(__uint_as_float(lo), __uint_as_float(hi));
}
__device__ __forceinline__ uint32_t smem_u32(const void* p) {
    return (uint32_t)__cvta_generic_to_shared(p);
}
// Fast accurate-enough tanh: ~1e-7 rel err, MUFU-based (no branches).
__device__ __forceinline__ float tanh_fast(float x) {
    float xc = fminf(fmaxf(x, -9.0f), 9.0f);     // tanh(9)=1-3e-8
    float e  = __expf(2.0f * xc);
    return __fdividef(e - 1.0f, e + 1.0f);
}

// ---------------------------------------------------------------------------
// Projection GEMM: out[M,256] = A[M,256] @ W[256,256]^T + bias
// (unchanged: ~214us each)
// ---------------------------------------------------------------------------
__global__ void __launch_bounds__(256, 2)
gemm_bias(const float* __restrict__ A, const float* __restrict__ W,
          const float* __restrict__ bias, float* __restrict__ out)
{
    __shared__ __align__(16) float As[16][128];
    __shared__ __align__(16) float Bs[16][64];

    const int tid = threadIdx.x;
    const int m0  = blockIdx.x * 128;
    const int n0  = blockIdx.y * 64;
    const int tx  = tid & 15;
    const int ty  = tid >> 4;
    const int lm  = tid >> 1;
    const int ak  = (tid & 1) * 8;
    const int ln  = tid & 63;
    const int bk  = (tid >> 6) * 4;

    unsigned long long acc[4][4];
#pragma unroll
    for (int p = 0; p < 4; p++)
#pragma unroll
        for (int n = 0; n < 4; n++) acc[p][n] = 0ull;

    const float* Arow = A + (size_t)(m0 + lm) * H_;
    const float* Wrow = W + (size_t)(n0 + ln) * H_;

    for (int k0 = 0; k0 < H_; k0 += 16) {
        float4 av0 = *(const float4*)(Arow + k0 + ak);
        float4 av1 = *(const float4*)(Arow + k0 + ak + 4);
        float4 bv0 = *(const float4*)(Wrow + k0 + bk);
        As[ak+0][lm] = av0.x; As[ak+1][lm] = av0.y;
        As[ak+2][lm] = av0.z; As[ak+3][lm] = av0.w;
        As[ak+4][lm] = av1.x; As[ak+5][lm] = av1.y;
        As[ak+6][lm] = av1.z; As[ak+7][lm] = av1.w;
        Bs[bk+0][ln] = bv0.x; Bs[bk+1][ln] = bv0.y;
        Bs[bk+2][ln] = bv0.z; Bs[bk+3][ln] = bv0.w;
        __syncthreads();
#pragma unroll
        for (int k = 0; k < 16; k++) {
            const ulonglong2* ap = (const ulonglong2*)&As[k][ty * 8];
            ulonglong2 q0 = ap[0];
            ulonglong2 q1 = ap[1];
            float4 bv = *(const float4*)&Bs[k][tx * 4];
            unsigned long long b0 = pack2(bv.x, bv.x);
            unsigned long long b1 = pack2(bv.y, bv.y);
            unsigned long long b2 = pack2(bv.z, bv.z);
            unsigned long long b3 = pack2(bv.w, bv.w);
            acc[0][0]=ffma2(q0.x,b0,acc[0][0]); acc[0][1]=ffma2(q0.x,b1,acc[0][1]);
            acc[0][2]=ffma2(q0.x,b2,acc[0][2]); acc[0][3]=ffma2(q0.x,b3,acc[0][3]);
            acc[1][0]=ffma2(q0.y,b0,acc[1][0]); acc[1][1]=ffma2(q0.y,b1,acc[1][1]);
            acc[1][2]=ffma2(q0.y,b2,acc[1][2]); acc[1][3]=ffma2(q0.y,b3,acc[1][3]);
            acc[2][0]=ffma2(q1.x,b0,acc[2][0]); acc[2][1]=ffma2(q1.x,b1,acc[2][1]);
            acc[2][2]=ffma2(q1.x,b2,acc[2][2]); acc[2][3]=ffma2(q1.x,b3,acc[2][3]);
            acc[3][0]=ffma2(q1.y,b0,acc[3][0]); acc[3][1]=ffma2(q1.y,b1,acc[3][1]);
            acc[3][2]=ffma2(q1.y,b2,acc[3][2]); acc[3][3]=ffma2(q1.y,b3,acc[3][3]);
        }
        __syncthreads();
    }

    float4 bb = *(const float4*)(bias + n0 + tx * 4);
#pragma unroll
    for (int p = 0; p < 4; p++) {
        float2 c0 = unpack2(acc[p][0]);
        float2 c1 = unpack2(acc[p][1]);
        float2 c2 = unpack2(acc[p][2]);
        float2 c3 = unpack2(acc[p][3]);
        float4 lo = make_float4(c0.x + bb.x, c1.x + bb.y, c2.x + bb.z, c3.x + bb.w);
        float4 hi = make_float4(c0.y + bb.x, c1.y + bb.y, c2.y + bb.z, c3.y + bb.w);
        size_t r = (size_t)(m0 + ty * 8 + 2 * p) * H_ + n0 + tx * 4;
        *(float4*)(out + r)      = lo;
        *(float4*)(out + r + H_) = hi;
    }
}

// ---------------------------------------------------------------------------
// Recurrent scan, round 11: NB=2 + 512-thread cluster CTAs.
//  Round-10 lesson: full-RF W_hh is impossible (weights alone = 64K regs).
//  Keep the proven cluster partial-sum handshake (round 8) and the proven
//  NB=2 handshake amortization (round 9), but with 512 threads/CTA:
//   - thread t: output j=t>>1, k-quarter kq=t&1 (64-wide dot, w=64 regs).
//   - shfl.xor(1) combines the two k-segments -> full local-128 partial.
//   - 4 warps/SMSP (2x latency hiding) and 32-FFMA2 chains (2x shorter).
//   - W_hh regs shared across both interleaved batches.
//  h-half stored as two 64-float segments at stride 68 (bank-disjoint for
//  even/odd lanes). Grid = (B_/NB)*2 = 64 CTAs x 512 thr.
// ---------------------------------------------------------------------------
__device__ __forceinline__ void mbar_wait_cta(uint32_t mbar, uint32_t parity) {
    asm volatile(
        "{\n\t"
        ".reg .pred P;\n"
        "WAIT_%=:\n\t"
        "mbarrier.try_wait.parity.shared::cta.b64 P, [%0], %1, 0x989680;\n\t"
        "@!P bra WAIT_%=;\n\t"
        "}"
        :: "r"(mbar), "r"(parity) : "memory");
}

__global__ void __launch_bounds__(512, 1) __cluster_dims__(2, 1, 1)
elman_scan(const float* __restrict__ xp, const float* __restrict__ Whh,
           float* __restrict__ ys)
{
    __shared__ __align__(16) float hs[NB][2][136];  // local h-half: 2 segs @68
    __shared__ __align__(16) float pb[NB][2][128];  // peer partials
    __shared__ __align__(8)  unsigned long long mbar[NB][2];

    const int tid  = threadIdx.x;
    const int rank = (int)(blockIdx.x & 1);
    const int b0   = (int)(blockIdx.x >> 1) * NB;
    const int kq   = tid & 1;          // k-quarter within local half
    const int j    = tid >> 1;         // output index [0,256)
    const int jl   = j & 127;
    const int lane = tid & 31;
    const bool mine = ((tid >> 8) == rank);

    // Weights: W_hh[j][rank*128 + kq*64 .. +63] as 32 packed f32x2 (64 regs)
    unsigned long long w[32];
    {
        const ulonglong2* wv = (const ulonglong2*)
            (Whh + (size_t)j * H_ + rank * 128 + kq * 64);
#pragma unroll
        for (int i = 0; i < 16; i++) {
            ulonglong2 v = wv[i];
            w[2*i] = v.x; w[2*i+1] = v.y;
        }
    }

    for (int i = tid; i < NB * 2 * 136; i += 512) (&hs[0][0][0])[i] = 0.0f;
    const uint32_t mb0 = smem_u32(&mbar[0][0]);
    const int leader = rank << 8;      // even, mine
    if (tid == 0) {
#pragma unroll
        for (int i = 0; i < 2 * NB; i++)
            asm volatile("mbarrier.init.shared.b64 [%0], 1;"
                         :: "r"(mb0 + (uint32_t)i * 8u) : "memory");
    }
    __syncthreads();
    if (tid == leader) {   // arm phase 0 of all (batch, buffer) barriers
#pragma unroll
        for (int i = 0; i < 2 * NB; i++)
            asm volatile("mbarrier.arrive.expect_tx.shared.b64 _, [%0], %1;"
                         :: "r"(mb0 + (uint32_t)i * 8u), "r"(512u) : "memory");
    }
    __syncthreads();
    asm volatile("barrier.cluster.arrive.aligned;" ::: "memory");
    asm volatile("barrier.cluster.wait.aligned;"   ::: "memory");

    const uint32_t pb0 = smem_u32(&pb[0][0][0]);
    uint32_t peer_pb, peer_mb;
    asm("mapa.shared::cluster.u32 %0, %1, %2;" : "=r"(peer_pb) : "r"(pb0), "r"(rank ^ 1));
    asm("mapa.shared::cluster.u32 %0, %1, %2;" : "=r"(peer_mb) : "r"(mb0), "r"(rank ^ 1));

    const float* xpb[NB];
    float*       ysb[NB];
#pragma unroll
    for (int b = 0; b < NB; b++) {
        xpb[b] = xp + (size_t)(b0 + b) * T_ * H_;
        ysb[b] = ys + (size_t)(b0 + b) * T_ * H_;
    }

    float x_cur[NB], x_next[NB];
#pragma unroll
    for (int b = 0; b < NB; b++) {
        x_cur[b] = 0.0f; x_next[b] = 0.0f;
        if (mine && kq == 0) x_cur[b] = __ldg(xpb[b] + j);
    }

    for (int t = 0; t < T_; t++) {
        const uint32_t buf = (uint32_t)(t & 1);
        float tot[NB];
        // ---- compute + send per batch (B overlaps A's DSMEM flight) ------
#pragma unroll
        for (int b = 0; b < NB; b++) {
            const ulonglong2* hv =
                (const ulonglong2*)&hs[b][buf][kq * 68];
            unsigned long long a0 = 0ull, a1 = 0ull, a2 = 0ull, a3 = 0ull;
#pragma unroll
            for (int i = 0; i < 8; i++) {
                ulonglong2 p = hv[2*i];
                ulonglong2 q = hv[2*i + 1];
                a0 = ffma2(w[4*i+0], p.x, a0);
                a1 = ffma2(w[4*i+1], p.y, a1);
                a2 = ffma2(w[4*i+2], q.x, a2);
                a3 = ffma2(w[4*i+3], q.y, a3);
            }
            float2 f0 = unpack2(a0), f1 = unpack2(a1);
            float2 f2 = unpack2(a2), f3 = unpack2(a3);
            float s = ((f0.x + f0.y) + (f1.x + f1.y)) +
                      ((f2.x + f2.y) + (f3.x + f3.y));
            tot[b] = s + __shfl_xor_sync(0xFFFFFFFFu, s, 1);
            if (!mine) {
                // lanes 2l, 2l+1 both hold output j's full partial; gather 4
                // consecutive outputs into lanes 0,8,16,24 and send 16B.
                float v1 = __shfl_down_sync(0xFFFFFFFFu, tot[b], 2);
                float v2 = __shfl_down_sync(0xFFFFFFFFu, tot[b], 4);
                float v3 = __shfl_down_sync(0xFFFFFFFFu, tot[b], 6);
                if ((lane & 7) == 0) {
                    asm volatile(
                        "st.async.shared::cluster.mbarrier::complete_tx::bytes"
                        ".v4.b32 [%0], {%1, %2, %3, %4}, [%5];"
                        :: "r"(peer_pb + (uint32_t)((b * 2 + (int)buf) * 128
                                                    + jl) * 4u),
                           "r"(__float_as_uint(tot[b])),
                           "r"(__float_as_uint(v1)),
                           "r"(__float_as_uint(v2)),
                           "r"(__float_as_uint(v3)),
                           "r"(peer_mb + (uint32_t)(b * 2 + (int)buf) * 8u)
                        : "memory");
                }
            }
        }
        // ---- wait + finish (even mine threads only) ----------------------
        if (mine && kq == 0) {
            const uint32_t par = (uint32_t)((t >> 1) & 1);
#pragma unroll
            for (int b = 0; b < NB; b++)
                if (t + 1 < T_)
                    x_next[b] = __ldg(xpb[b] + (size_t)(t + 1) * H_ + j);
#pragma unroll
            for (int b = 0; b < NB; b++) {
                const uint32_t mboff = (uint32_t)(b * 2 + (int)buf) * 8u;
                mbar_wait_cta(mb0 + mboff, par);
                if (tid == leader && t + 2 < T_) {
                    asm volatile(
                        "mbarrier.arrive.expect_tx.shared.b64 _, [%0], %1;"
                        :: "r"(mb0 + mboff), "r"(512u) : "memory");
                }
                float v = tanh_fast(tot[b] + pb[b][buf][jl] + x_cur[b]);
                hs[b][buf ^ 1u][(jl >> 6) * 68 + (jl & 63)] = v;
                ysb[b][(size_t)t * H_ + j] = v;
                x_cur[b] = x_next[b];
            }
        }
        __syncthreads();   // h[t+1] visible; orders pb read before reuse
    }
}

// ---------------------------------------------------------------------------
// Launch: gemm0 -> scan0 -> gemm1 -> scan1 (all on the capture stream)
// ---------------------------------------------------------------------------
extern "C" void kernel_launch(void* const* d_in, const int* in_sizes, int n_in,
                              void* d_out, int out_size)
{
    const float* x     = (const float*)d_in[0];
    const float* W_ih0 = (const float*)d_in[1];
    const float* b_ih0 = (const float*)d_in[2];
    const float* W_hh0 = (const float*)d_in[3];
    const float* W_ih1 = (const float*)d_in[4];
    const float* b_ih1 = (const float*)d_in[5];
    const float* W_hh1 = (const float*)d_in[6];
    float* out = (float*)d_out;

    float *xp, *h;
    cudaGetSymbolAddress((void**)&xp, g_xp);
    cudaGetSymbolAddress((void**)&h,  g_h);

    dim3 ggrid(M_ / 128, H_ / 64);   // (512, 4)

    gemm_bias<<<ggrid, 256>>>(x, W_ih0, b_ih0, xp);
    elman_scan<<<(B_ / NB) * 2, 512>>>(xp, W_hh0, h);
    gemm_bias<<<ggrid, 256>>>(h, W_ih1, b_ih1, xp);
    elman_scan<<<(B_ / NB) * 2, 512>>>(xp, W_hh1, out);
}

// round 12
// speedup vs baseline: 1.7707x; 1.3730x over previous
#include <cuda_runtime.h>
#include <math.h>
#include <stdint.h>

#define B_ 64
#define T_ 1024
#define H_ 256
#define M_ (B_*T_)   /* 65536 rows for the projection GEMMs */

// Scratch (device globals — no runtime allocation allowed)
__device__ float g_xp[B_*T_*H_];   // input-projection result for current layer
__device__ float g_h [B_*T_*H_];   // layer-0 hidden sequence

// ---------------------------------------------------------------------------
// packed f32x2 helpers (sm_100+): one instr = 2 fp32 FMAs
// ---------------------------------------------------------------------------
__device__ __forceinline__ unsigned long long ffma2(unsigned long long a,
                                                    unsigned long long b,
                                                    unsigned long long c) {
    unsigned long long d;
    asm("fma.rn.f32x2 %0, %1, %2, %3;" : "=l"(d) : "l"(a), "l"(b), "l"(c));
    return d;
}
__device__ __forceinline__ unsigned long long pack2(float lo, float hi) {
    unsigned long long r;
    asm("mov.b64 %0, {%1, %2};"
        : "=l"(r) : "r"(__float_as_uint(lo)), "r"(__float_as_uint(hi)));
    return r;
}
__device__ __forceinline__ float2 unpack2(unsigned long long v) {
    uint32_t lo, hi;
    asm("mov.b64 {%0, %1}, %2;" : "=r"(lo), "=r"(hi) : "l"(v));
    return make_float2(__uint_as_float(lo), __uint_as_float(hi));
}
__device__ __forceinline__ uint32_t smem_u32(const void* p) {
    return (uint32_t)__cvta_generic_to_shared(p);
}
// Fast accurate-enough tanh: ~1e-7 rel err, MUFU-based (no branches).
__device__ __forceinline__ float tanh_fast(float x) {
    float xc = fminf(fmaxf(x, -9.0f), 9.0f);     // tanh(9)=1-3e-8
    float e  = __expf(2.0f * xc);
    return __fdividef(e - 1.0f, e + 1.0f);
}

// ---------------------------------------------------------------------------
// Projection GEMM: out[M,256] = A[M,256] @ W[256,256]^T + bias
// (unchanged: ~214us each)
// ---------------------------------------------------------------------------
__global__ void __launch_bounds__(256, 2)
gemm_bias(const float* __restrict__ A, const float* __restrict__ W,
          const float* __restrict__ bias, float* __restrict__ out)
{
    __shared__ __align__(16) float As[16][128];
    __shared__ __align__(16) float Bs[16][64];

    const int tid = threadIdx.x;
    const int m0  = blockIdx.x * 128;
    const int n0  = blockIdx.y * 64;
    const int tx  = tid & 15;
    const int ty  = tid >> 4;
    const int lm  = tid >> 1;
    const int ak  = (tid & 1) * 8;
    const int ln  = tid & 63;
    const int bk  = (tid >> 6) * 4;

    unsigned long long acc[4][4];
#pragma unroll
    for (int p = 0; p < 4; p++)
#pragma unroll
        for (int n = 0; n < 4; n++) acc[p][n] = 0ull;

    const float* Arow = A + (size_t)(m0 + lm) * H_;
    const float* Wrow = W + (size_t)(n0 + ln) * H_;

    for (int k0 = 0; k0 < H_; k0 += 16) {
        float4 av0 = *(const float4*)(Arow + k0 + ak);
        float4 av1 = *(const float4*)(Arow + k0 + ak + 4);
        float4 bv0 = *(const float4*)(Wrow + k0 + bk);
        As[ak+0][lm] = av0.x; As[ak+1][lm] = av0.y;
        As[ak+2][lm] = av0.z; As[ak+3][lm] = av0.w;
        As[ak+4][lm] = av1.x; As[ak+5][lm] = av1.y;
        As[ak+6][lm] = av1.z; As[ak+7][lm] = av1.w;
        Bs[bk+0][ln] = bv0.x; Bs[bk+1][ln] = bv0.y;
        Bs[bk+2][ln] = bv0.z; Bs[bk+3][ln] = bv0.w;
        __syncthreads();
#pragma unroll
        for (int k = 0; k < 16; k++) {
            const ulonglong2* ap = (const ulonglong2*)&As[k][ty * 8];
            ulonglong2 q0 = ap[0];
            ulonglong2 q1 = ap[1];
            float4 bv = *(const float4*)&Bs[k][tx * 4];
            unsigned long long b0 = pack2(bv.x, bv.x);
            unsigned long long b1 = pack2(bv.y, bv.y);
            unsigned long long b2 = pack2(bv.z, bv.z);
            unsigned long long b3 = pack2(bv.w, bv.w);
            acc[0][0]=ffma2(q0.x,b0,acc[0][0]); acc[0][1]=ffma2(q0.x,b1,acc[0][1]);
            acc[0][2]=ffma2(q0.x,b2,acc[0][2]); acc[0][3]=ffma2(q0.x,b3,acc[0][3]);
            acc[1][0]=ffma2(q0.y,b0,acc[1][0]); acc[1][1]=ffma2(q0.y,b1,acc[1][1]);
            acc[1][2]=ffma2(q0.y,b2,acc[1][2]); acc[1][3]=ffma2(q0.y,b3,acc[1][3]);
            acc[2][0]=ffma2(q1.x,b0,acc[2][0]); acc[2][1]=ffma2(q1.x,b1,acc[2][1]);
            acc[2][2]=ffma2(q1.x,b2,acc[2][2]); acc[2][3]=ffma2(q1.x,b3,acc[2][3]);
            acc[3][0]=ffma2(q1.y,b0,acc[3][0]); acc[3][1]=ffma2(q1.y,b1,acc[3][1]);
            acc[3][2]=ffma2(q1.y,b2,acc[3][2]); acc[3][3]=ffma2(q1.y,b3,acc[3][3]);
        }
        __syncthreads();
    }

    float4 bb = *(const float4*)(bias + n0 + tx * 4);
#pragma unroll
    for (int p = 0; p < 4; p++) {
        float2 c0 = unpack2(acc[p][0]);
        float2 c1 = unpack2(acc[p][1]);
        float2 c2 = unpack2(acc[p][2]);
        float2 c3 = unpack2(acc[p][3]);
        float4 lo = make_float4(c0.x + bb.x, c1.x + bb.y, c2.x + bb.z, c3.x + bb.w);
        float4 hi = make_float4(c0.y + bb.x, c1.y + bb.y, c2.y + bb.z, c3.y + bb.w);
        size_t r = (size_t)(m0 + ty * 8 + 2 * p) * H_ + n0 + tx * 4;
        *(float4*)(out + r)      = lo;
        *(float4*)(out + r + H_) = hi;
    }
}

// ---------------------------------------------------------------------------
// Recurrent scan, round 12: round-8 skeleton, barrier-free inner loop.
//  - Same partial-sum exchange (CTA r owns h-half r; thread j = tid does a
//    full 128-wide local-k dot; peer partials cross via st.async).
//  - NEW: per-step __syncthreads deleted. Local h propagation is ALSO
//    st.async (to own SMEM) tx-counted on hbar[buf]; all threads wait
//    hbar[t&1] at step t (t>=1). Sender warps thus decouple from the
//    mine-warps' tanh/store tails.
//  - NEW: scalar sends (no shfl gather — 3 dependent SHFLs ~78cyc were on
//    the send path; round 8 showed per-message cost is far smaller).
//  - NEW: 8 accumulator chains (depth 32cyc instead of 64).
//  Ordering audit (all plain-LDS reads after try_wait are legal because
//  complete_tx makes data visible at phase completion — validated r6-r8):
//   * WAR hs[buf]: writer at t+1 (targets hs[t&1]) is gated by pbar[t+1]
//     completion <- peer sends at t+1 <- (sender program order) sender read
//     of hs[t&1] at t. Safe.
//   * WAR pb[buf]: remote writes at t+2 gated by peer hbar completion at
//     t+1 <- all 128 mine h-arrivals <- each mine thread's pb read at t.
//   * Re-arms (by leader, right after its own wait) open phase P+1 before
//     any P+1 arrival: P+1 arrivals are gated through pbar waits that
//     transitively require the leader's prior-step h-send (program-order
//     after its re-arm). Parity waits by other threads on completed phase P
//     pass regardless. Safe.
//  mbar layout: [0]=pbar buf0, [1]=pbar buf1, [2]=hbar buf0, [3]=hbar buf1.
// ---------------------------------------------------------------------------
__device__ __forceinline__ void mbar_wait_cta(uint32_t mbar, uint32_t parity) {
    asm volatile(
        "{\n\t"
        ".reg .pred P;\n"
        "WAIT_%=:\n\t"
        "mbarrier.try_wait.parity.shared::cta.b64 P, [%0], %1, 0x989680;\n\t"
        "@!P bra WAIT_%=;\n\t"
        "}"
        :: "r"(mbar), "r"(parity) : "memory");
}

__global__ void __launch_bounds__(256, 1) __cluster_dims__(2, 1, 1)
elman_scan(const float* __restrict__ xp, const float* __restrict__ Whh,
           float* __restrict__ ys)
{
    __shared__ __align__(16) float hs[2][128];     // local h half, double-buf
    __shared__ __align__(16) float pb[2][128];     // peer partials, double-buf
    __shared__ __align__(8)  unsigned long long mbar[4];

    const int tid  = threadIdx.x;
    const int rank = (int)(blockIdx.x & 1);
    const int batch= (int)(blockIdx.x >> 1);
    const int j    = tid;              // global output index owned by thread
    const int jl   = tid & 127;        // index within its half
    const bool mine = ((tid >> 7) == rank);   // my-half warps (4 of 8)

    // Weights: W_hh[j][rank*128 .. +127] as 64 packed f32x2 (local k-half)
    unsigned long long w[64];
    {
        const ulonglong2* wv =
            (const ulonglong2*)(Whh + (size_t)j * H_ + rank * 128);
#pragma unroll
        for (int i = 0; i < 32; i++) {
            ulonglong2 v = wv[i];
            w[2*i] = v.x; w[2*i+1] = v.y;
        }
    }

    if (tid < 128) { hs[0][tid] = 0.0f; hs[1][tid] = 0.0f; }
    const uint32_t mb0 = smem_u32(&mbar[0]);
    const int leader = rank << 7;      // a my-half thread
    if (tid == 0) {
#pragma unroll
        for (int i = 0; i < 4; i++)
            asm volatile("mbarrier.init.shared.b64 [%0], 1;"
                         :: "r"(mb0 + (uint32_t)i * 8u) : "memory");
    }
    __syncthreads();
    if (tid == leader) {   // arm phase 0 of pbar[0..1], hbar[0..1]
#pragma unroll
        for (int i = 0; i < 4; i++)
            asm volatile("mbarrier.arrive.expect_tx.shared.b64 _, [%0], %1;"
                         :: "r"(mb0 + (uint32_t)i * 8u), "r"(512u) : "memory");
    }
    __syncthreads();
    // inits/arms visible cluster-wide before any remote traffic
    asm volatile("barrier.cluster.arrive.aligned;" ::: "memory");
    asm volatile("barrier.cluster.wait.aligned;"   ::: "memory");

    const uint32_t pb0 = smem_u32(&pb[0][0]);
    const uint32_t hs0 = smem_u32(&hs[0][0]);
    uint32_t peer_pb, peer_mb, self_hs, self_mb;
    asm("mapa.shared::cluster.u32 %0, %1, %2;" : "=r"(peer_pb) : "r"(pb0), "r"(rank ^ 1));
    asm("mapa.shared::cluster.u32 %0, %1, %2;" : "=r"(peer_mb) : "r"(mb0), "r"(rank ^ 1));
    asm("mapa.shared::cluster.u32 %0, %1, %2;" : "=r"(self_hs) : "r"(hs0), "r"(rank));
    asm("mapa.shared::cluster.u32 %0, %1, %2;" : "=r"(self_mb) : "r"(mb0), "r"(rank));

    const float* xpb = xp + (size_t)batch * T_ * H_;
    float*       ysb = ys + (size_t)batch * T_ * H_;

    float x_cur = 0.0f, x_next = 0.0f;
    if (mine) x_cur = __ldg(xpb + j);      // xp[t=0][j]

    for (int t = 0; t < T_; t++) {
        const uint32_t buf = (uint32_t)(t & 1);
        // --- wait for h[t] (written at t-1 via st.async on hbar[buf]) -----
        if (t) {
            mbar_wait_cta(mb0 + (2u + buf) * 8u,
                          (uint32_t)(((t - 1) >> 1) & 1));
            if (tid == leader && t + 2 < T_) {
                asm volatile("mbarrier.arrive.expect_tx.shared.b64 _, [%0], %1;"
                             :: "r"(mb0 + (2u + buf) * 8u), "r"(512u)
                             : "memory");
            }
        }

        // --- local-k partial: 8 chains of 8 FFMA2 (depth 32cyc) -----------
        const ulonglong2* hv = (const ulonglong2*)&hs[buf][0];
        unsigned long long a0=0ull,a1=0ull,a2=0ull,a3=0ull,
                           a4=0ull,a5=0ull,a6=0ull,a7=0ull;
#pragma unroll
        for (int i = 0; i < 8; i++) {
            ulonglong2 p = hv[4*i];
            ulonglong2 q = hv[4*i + 1];
            ulonglong2 r = hv[4*i + 2];
            ulonglong2 u = hv[4*i + 3];
            a0 = ffma2(w[8*i+0], p.x, a0);
            a1 = ffma2(w[8*i+1], p.y, a1);
            a2 = ffma2(w[8*i+2], q.x, a2);
            a3 = ffma2(w[8*i+3], q.y, a3);
            a4 = ffma2(w[8*i+4], r.x, a4);
            a5 = ffma2(w[8*i+5], r.y, a5);
            a6 = ffma2(w[8*i+6], u.x, a6);
            a7 = ffma2(w[8*i+7], u.y, a7);
        }
        float2 f0=unpack2(a0), f1=unpack2(a1), f2=unpack2(a2), f3=unpack2(a3);
        float2 f4=unpack2(a4), f5=unpack2(a5), f6=unpack2(a6), f7=unpack2(a7);
        float s = (((f0.x+f0.y)+(f1.x+f1.y)) + ((f2.x+f2.y)+(f3.x+f3.y))) +
                  (((f4.x+f4.y)+(f5.x+f5.y)) + ((f6.x+f6.y)+(f7.x+f7.y)));

        if (!mine) {
            // Ship the partial immediately — scalar message, no shfl stage.
            asm volatile(
                "st.async.shared::cluster.mbarrier::complete_tx::bytes.b32 "
                "[%0], %1, [%2];"
                :: "r"(peer_pb + (buf * 128u + (uint32_t)jl) * 4u),
                   "r"(__float_as_uint(s)),
                   "r"(peer_mb + buf * 8u) : "memory");
        } else {
            if (t + 1 < T_)
                x_next = __ldg(xpb + (size_t)(t + 1) * H_ + j);
            mbar_wait_cta(mb0 + buf * 8u, (uint32_t)((t >> 1) & 1));
            if (tid == leader && t + 2 < T_) {
                asm volatile("mbarrier.arrive.expect_tx.shared.b64 _, [%0], %1;"
                             :: "r"(mb0 + buf * 8u), "r"(512u) : "memory");
            }
            float v = tanh_fast(s + pb[buf][jl] + x_cur);
            ysb[(size_t)t * H_ + j] = v;
            if (t + 1 < T_) {
                // Local h propagation: async store to OWN SMEM, tx-counted
                // on hbar[(t+1)&1]; replaces the per-step __syncthreads.
                asm volatile(
                    "st.async.shared::cluster.mbarrier::complete_tx::bytes.b32 "
                    "[%0], %1, [%2];"
                    :: "r"(self_hs + ((buf ^ 1u) * 128u + (uint32_t)jl) * 4u),
                       "r"(__float_as_uint(v)),
                       "r"(self_mb + (2u + (buf ^ 1u)) * 8u) : "memory");
            }
            x_cur = x_next;
        }
    }
}

// ---------------------------------------------------------------------------
// Launch: gemm0 -> scan0 -> gemm1 -> scan1 (all on the capture stream)
// ---------------------------------------------------------------------------
extern "C" void kernel_launch(void* const* d_in, const int* in_sizes, int n_in,
                              void* d_out, int out_size)
{
    const float* x     = (const float*)d_in[0];
    const float* W_ih0 = (const float*)d_in[1];
    const float* b_ih0 = (const float*)d_in[2];
    const float* W_hh0 = (const float*)d_in[3];
    const float* W_ih1 = (const float*)d_in[4];
    const float* b_ih1 = (const float*)d_in[5];
    const float* W_hh1 = (const float*)d_in[6];
    float* out = (float*)d_out;

    float *xp, *h;
    cudaGetSymbolAddress((void**)&xp, g_xp);
    cudaGetSymbolAddress((void**)&h,  g_h);

    dim3 ggrid(M_ / 128, H_ / 64);   // (512, 4)

    gemm_bias<<<ggrid, 256>>>(x, W_ih0, b_ih0, xp);
    elman_scan<<<B_ * 2, 256>>>(xp, W_hh0, h);
    gemm_bias<<<ggrid, 256>>>(h, W_ih1, b_ih1, xp);
    elman_scan<<<B_ * 2, 256>>>(xp, W_hh1, out);
}

// round 13
// speedup vs baseline: 1.9616x; 1.1078x over previous
#include <cuda_runtime.h>
#include <math.h>
#include <stdint.h>

#define B_ 64
#define T_ 1024
#define H_ 256
#define M_ (B_*T_)   /* 65536 rows for the projection GEMMs */

// Scratch (device globals — no runtime allocation allowed)
__device__ float g_xp[B_*T_*H_];   // input-projection result for current layer
__device__ float g_h [B_*T_*H_];   // layer-0 hidden sequence

// ---------------------------------------------------------------------------
// packed f32x2 helpers (sm_100+): one instr = 2 fp32 FMAs
// ---------------------------------------------------------------------------
__device__ __forceinline__ unsigned long long ffma2(unsigned long long a,
                                                    unsigned long long b,
                                                    unsigned long long c) {
    unsigned long long d;
    asm("fma.rn.f32x2 %0, %1, %2, %3;" : "=l"(d) : "l"(a), "l"(b), "l"(c));
    return d;
}
__device__ __forceinline__ unsigned long long pack2(float lo, float hi) {
    unsigned long long r;
    asm("mov.b64 %0, {%1, %2};"
        : "=l"(r) : "r"(__float_as_uint(lo)), "r"(__float_as_uint(hi)));
    return r;
}
__device__ __forceinline__ float2 unpack2(unsigned long long v) {
    uint32_t lo, hi;
    asm("mov.b64 {%0, %1}, %2;" : "=r"(lo), "=r"(hi) : "l"(v));
    return make_float2(__uint_as_float(lo), __uint_as_float(hi));
}
__device__ __forceinline__ uint32_t smem_u32(const void* p) {
    return (uint32_t)__cvta_generic_to_shared(p);
}
// Fast accurate-enough tanh: ~1e-7 rel err, MUFU-based (no branches).
__device__ __forceinline__ float tanh_fast(float x) {
    float xc = fminf(fmaxf(x, -9.0f), 9.0f);     // tanh(9)=1-3e-8
    float e  = __expf(2.0f * xc);
    return __fdividef(e - 1.0f, e + 1.0f);
}

// ---------------------------------------------------------------------------
// Projection GEMM: out[M,256] = A[M,256] @ W[256,256]^T + bias
// (unchanged: ~214us each)
// ---------------------------------------------------------------------------
__global__ void __launch_bounds__(256, 2)
gemm_bias(const float* __restrict__ A, const float* __restrict__ W,
          const float* __restrict__ bias, float* __restrict__ out)
{
    __shared__ __align__(16) float As[16][128];
    __shared__ __align__(16) float Bs[16][64];

    const int tid = threadIdx.x;
    const int m0  = blockIdx.x * 128;
    const int n0  = blockIdx.y * 64;
    const int tx  = tid & 15;
    const int ty  = tid >> 4;
    const int lm  = tid >> 1;
    const int ak  = (tid & 1) * 8;
    const int ln  = tid & 63;
    const int bk  = (tid >> 6) * 4;

    unsigned long long acc[4][4];
#pragma unroll
    for (int p = 0; p < 4; p++)
#pragma unroll
        for (int n = 0; n < 4; n++) acc[p][n] = 0ull;

    const float* Arow = A + (size_t)(m0 + lm) * H_;
    const float* Wrow = W + (size_t)(n0 + ln) * H_;

    for (int k0 = 0; k0 < H_; k0 += 16) {
        float4 av0 = *(const float4*)(Arow + k0 + ak);
        float4 av1 = *(const float4*)(Arow + k0 + ak + 4);
        float4 bv0 = *(const float4*)(Wrow + k0 + bk);
        As[ak+0][lm] = av0.x; As[ak+1][lm] = av0.y;
        As[ak+2][lm] = av0.z; As[ak+3][lm] = av0.w;
        As[ak+4][lm] = av1.x; As[ak+5][lm] = av1.y;
        As[ak+6][lm] = av1.z; As[ak+7][lm] = av1.w;
        Bs[bk+0][ln] = bv0.x; Bs[bk+1][ln] = bv0.y;
        Bs[bk+2][ln] = bv0.z; Bs[bk+3][ln] = bv0.w;
        __syncthreads();
#pragma unroll
        for (int k = 0; k < 16; k++) {
            const ulonglong2* ap = (const ulonglong2*)&As[k][ty * 8];
            ulonglong2 q0 = ap[0];
            ulonglong2 q1 = ap[1];
            float4 bv = *(const float4*)&Bs[k][tx * 4];
            unsigned long long b0 = pack2(bv.x, bv.x);
            unsigned long long b1 = pack2(bv.y, bv.y);
            unsigned long long b2 = pack2(bv.z, bv.z);
            unsigned long long b3 = pack2(bv.w, bv.w);
            acc[0][0]=ffma2(q0.x,b0,acc[0][0]); acc[0][1]=ffma2(q0.x,b1,acc[0][1]);
            acc[0][2]=ffma2(q0.x,b2,acc[0][2]); acc[0][3]=ffma2(q0.x,b3,acc[0][3]);
            acc[1][0]=ffma2(q0.y,b0,acc[1][0]); acc[1][1]=ffma2(q0.y,b1,acc[1][1]);
            acc[1][2]=ffma2(q0.y,b2,acc[1][2]); acc[1][3]=ffma2(q0.y,b3,acc[1][3]);
            acc[2][0]=ffma2(q1.x,b0,acc[2][0]); acc[2][1]=ffma2(q1.x,b1,acc[2][1]);
            acc[2][2]=ffma2(q1.x,b2,acc[2][2]); acc[2][3]=ffma2(q1.x,b3,acc[2][3]);
            acc[3][0]=ffma2(q1.y,b0,acc[3][0]); acc[3][1]=ffma2(q1.y,b1,acc[3][1]);
            acc[3][2]=ffma2(q1.y,b2,acc[3][2]); acc[3][3]=ffma2(q1.y,b3,acc[3][3]);
        }
        __syncthreads();
    }

    float4 bb = *(const float4*)(bias + n0 + tx * 4);
#pragma unroll
    for (int p = 0; p < 4; p++) {
        float2 c0 = unpack2(acc[p][0]);
        float2 c1 = unpack2(acc[p][1]);
        float2 c2 = unpack2(acc[p][2]);
        float2 c3 = unpack2(acc[p][3]);
        float4 lo = make_float4(c0.x + bb.x, c1.x + bb.y, c2.x + bb.z, c3.x + bb.w);
        float4 hi = make_float4(c0.y + bb.x, c1.y + bb.y, c2.y + bb.z, c3.y + bb.w);
        size_t r = (size_t)(m0 + ty * 8 + 2 * p) * H_ + n0 + tx * 4;
        *(float4*)(out + r)      = lo;
        *(float4*)(out + r + H_) = hi;
    }
}

// ---------------------------------------------------------------------------
// Recurrent scan, round 13: round-8 skeleton, mbarriers replaced by
// TAGGED-WORD POLLING.
//  - Sender packs (partial fp32, tag=t+1) into ONE aligned 8-byte word and
//    fires a single weak st.shared::cluster.b64 to the peer's slot. Aligned
//    b64 is single-copy atomic: value+tag arrive together, so there is NO
//    data/flag ordering problem (the flag IS the word) — no fence, no
//    mbarrier, no tx accounting, no wakeup path.
//  - Receiver spins on ld.volatile.shared.b64 of its own slot until
//    tag == t+1 (~flight + one poll granularity).
//  - Tag safety: slot buf=t&1 carries tag t+1, distinct per use; overwrite
//    at t+2 is ordered by the per-step __syncthreads (sender writes t+2
//    only after passing bar(t+1) <- receiver's bar(t) arrival <- its read).
//    Tags start at 1; buffers zeroed before the init cluster sync.
//  - Local h: plain STS + the same single __syncthreads (round-12 showed
//    st.async for local data is a regression).
//  - 8 accumulator chains (dep depth 32 cyc).
//  Final step: receiver polls until tag T matches, so the last remote store
//  is consumed before either CTA exits.
// ---------------------------------------------------------------------------
__global__ void __launch_bounds__(256, 1) __cluster_dims__(2, 1, 1)
elman_scan(const float* __restrict__ xp, const float* __restrict__ Whh,
           float* __restrict__ ys)
{
    __shared__ __align__(16) float hs[2][128];              // local h half
    __shared__ __align__(16) unsigned long long pbt[2][128];// (val,tag) slots

    const int tid  = threadIdx.x;
    const int rank = (int)(blockIdx.x & 1);
    const int batch= (int)(blockIdx.x >> 1);
    const int j    = tid;              // global output index owned by thread
    const int jl   = tid & 127;        // index within its half
    const bool mine = ((tid >> 7) == rank);   // my-half warps (4 of 8)

    // Weights: W_hh[j][rank*128 .. +127] as 64 packed f32x2 (local k-half)
    unsigned long long w[64];
    {
        const ulonglong2* wv =
            (const ulonglong2*)(Whh + (size_t)j * H_ + rank * 128);
#pragma unroll
        for (int i = 0; i < 32; i++) {
            ulonglong2 v = wv[i];
            w[2*i] = v.x; w[2*i+1] = v.y;
        }
    }

    if (tid < 128) { hs[0][tid] = 0.0f; hs[1][tid] = 0.0f; }
    pbt[0][tid & 127] = 0ull;          // tags 0 (first real tag is 1)
    pbt[1][tid & 127] = 0ull;
    __syncthreads();
    // zeroed slots visible cluster-wide before any remote store can land
    asm volatile("barrier.cluster.arrive.aligned;" ::: "memory");
    asm volatile("barrier.cluster.wait.aligned;"   ::: "memory");

    const uint32_t pbt0 = smem_u32(&pbt[0][0]);
    uint32_t peer_pbt;
    asm("mapa.shared::cluster.u32 %0, %1, %2;"
        : "=r"(peer_pbt) : "r"(pbt0), "r"(rank ^ 1));
    const uint32_t my_slot = pbt0 + (uint32_t)jl * 8u;      // + buf*1024
    const uint32_t peer_slot = peer_pbt + (uint32_t)jl * 8u;

    const float* xpb = xp + (size_t)batch * T_ * H_;
    float*       ysb = ys + (size_t)batch * T_ * H_;

    float x_cur = 0.0f, x_next = 0.0f;
    if (mine) x_cur = __ldg(xpb + j);      // xp[t=0][j]

    for (int t = 0; t < T_; t++) {
        const uint32_t buf = (uint32_t)(t & 1);
        // --- local-k partial: 8 chains of 8 FFMA2 (depth 32cyc) -----------
        const ulonglong2* hv = (const ulonglong2*)&hs[buf][0];
        unsigned long long a0=0ull,a1=0ull,a2=0ull,a3=0ull,
                           a4=0ull,a5=0ull,a6=0ull,a7=0ull;
#pragma unroll
        for (int i = 0; i < 8; i++) {
            ulonglong2 p = hv[4*i];
            ulonglong2 q = hv[4*i + 1];
            ulonglong2 r = hv[4*i + 2];
            ulonglong2 u = hv[4*i + 3];
            a0 = ffma2(w[8*i+0], p.x, a0);
            a1 = ffma2(w[8*i+1], p.y, a1);
            a2 = ffma2(w[8*i+2], q.x, a2);
            a3 = ffma2(w[8*i+3], q.y, a3);
            a4 = ffma2(w[8*i+4], r.x, a4);
            a5 = ffma2(w[8*i+5], r.y, a5);
            a6 = ffma2(w[8*i+6], u.x, a6);
            a7 = ffma2(w[8*i+7], u.y, a7);
        }
        float2 f0=unpack2(a0), f1=unpack2(a1), f2=unpack2(a2), f3=unpack2(a3);
        float2 f4=unpack2(a4), f5=unpack2(a5), f6=unpack2(a6), f7=unpack2(a7);
        float s = (((f0.x+f0.y)+(f1.x+f1.y)) + ((f2.x+f2.y)+(f3.x+f3.y))) +
                  (((f4.x+f4.y)+(f5.x+f5.y)) + ((f6.x+f6.y)+(f7.x+f7.y)));

        if (!mine) {
            // One weak 8B store: (partial, tag). Single-copy atomic.
            unsigned long long msg;
            asm("mov.b64 %0, {%1, %2};"
                : "=l"(msg)
                : "r"(__float_as_uint(s)), "r"((uint32_t)(t + 1)));
            asm volatile("st.shared::cluster.b64 [%0], %1;"
                         :: "r"(peer_slot + buf * 1024u), "l"(msg)
                         : "memory");
        } else {
            if (t + 1 < T_)
                x_next = __ldg(xpb + (size_t)(t + 1) * H_ + j);
            // Spin until this step's tag shows up (value rides along).
            uint32_t lo, hi;
            const uint32_t addr = my_slot + buf * 1024u;
            const uint32_t want = (uint32_t)(t + 1);
            do {
                asm volatile("ld.volatile.shared.v2.u32 {%0, %1}, [%2];"
                             : "=r"(lo), "=r"(hi) : "r"(addr) : "memory");
            } while (hi != want);
            float v = tanh_fast(s + __uint_as_float(lo) + x_cur);
            ysb[(size_t)t * H_ + j] = v;
            if (t + 1 < T_) hs[buf ^ 1u][jl] = v;
            x_cur = x_next;
        }
        __syncthreads();   // h[t+1] visible; orders slot reuse (WAR fence)
    }
}

// ---------------------------------------------------------------------------
// Launch: gemm0 -> scan0 -> gemm1 -> scan1 (all on the capture stream)
// ---------------------------------------------------------------------------
extern "C" void kernel_launch(void* const* d_in, const int* in_sizes, int n_in,
                              void* d_out, int out_size)
{
    const float* x     = (const float*)d_in[0];
    const float* W_ih0 = (const float*)d_in[1];
    const float* b_ih0 = (const float*)d_in[2];
    const float* W_hh0 = (const float*)d_in[3];
    const float* W_ih1 = (const float*)d_in[4];
    const float* b_ih1 = (const float*)d_in[5];
    const float* W_hh1 = (const float*)d_in[6];
    float* out = (float*)d_out;

    float *xp, *h;
    cudaGetSymbolAddress((void**)&xp, g_xp);
    cudaGetSymbolAddress((void**)&h,  g_h);

    dim3 ggrid(M_ / 128, H_ / 64);   // (512, 4)

    gemm_bias<<<ggrid, 256>>>(x, W_ih0, b_ih0, xp);
    elman_scan<<<B_ * 2, 256>>>(xp, W_hh0, h);
    gemm_bias<<<ggrid, 256>>>(h, W_ih1, b_ih1, xp);
    elman_scan<<<B_ * 2, 256>>>(xp, W_hh1, out);
}